// round 4
// baseline (speedup 1.0000x reference)
#include <cuda_runtime.h>
#include <math.h>

#define PH 7
#define PW 7
#define C  256
#define MAXN 1024

// Scratch (device globals; no allocation allowed)
__device__ float4 g_sbox[MAXN];   // sorted normalized boxes (y1,x1,y2,x2)
__device__ int    g_slvl[MAXN];   // sorted levels

// ---------------------------------------------------------------------------
// Kernel 1: per-roi level + normalized box, stable counting sort via packed
// block-wide inclusive scan (4 levels x 16-bit counters in a uint64).
// Single block, 1024 threads, N <= 1024.
// ---------------------------------------------------------------------------
__global__ void level_sort_kernel(const float* __restrict__ rois, int N) {
    __shared__ unsigned long long s[1024];
    int i = threadIdx.x;

    int lvl = 0;
    float4 nb = make_float4(0.f, 0.f, 0.f, 0.f);
    unsigned long long v = 0ULL;

    if (i < N) {
        float y1 = rois[i * 4 + 0];
        float x1 = rois[i * 4 + 1];
        float y2 = rois[i * 4 + 2];
        float x2 = rois[i * 4 + 3];
        float h = y2 - y1;
        float w = x2 - x1;
        // match reference fp32 path: log(sqrt(h*w))/log(2) - 5, round-half-even
        float lf = logf(sqrtf(h * w)) * (1.0f / logf(2.0f)) - 5.0f;
        int l = (int)rintf(lf);
        l = min(max(l, 0), 3);
        lvl = l;
        const float inv = 1.0f / 1024.0f;
        nb = make_float4(y1 * inv, x1 * inv, y2 * inv, x2 * inv);
        v = 1ULL << (16 * lvl);
    }

    s[i] = v;
    __syncthreads();
#pragma unroll
    for (int off = 1; off < 1024; off <<= 1) {
        unsigned long long t = (i >= off) ? s[i - off] : 0ULL;
        __syncthreads();
        s[i] += t;
        __syncthreads();
    }

    if (i < N) {
        unsigned long long incl = s[i];
        unsigned long long total = s[1023];
        int rank = (int)((incl >> (16 * lvl)) & 0xFFFFULL) - 1;  // exclusive rank within level
        int base = 0;
#pragma unroll
        for (int l = 0; l < 4; l++)
            if (l < lvl) base += (int)((total >> (16 * l)) & 0xFFFFULL);
        int pos = base + rank;
        g_slvl[pos] = lvl;
        g_sbox[pos] = nb;
    }
}

// ---------------------------------------------------------------------------
// Kernel 2: bilinear crop_and_resize gather.
// grid = (N, PH); blockDim = C (256).  Thread = channel; unrolled px loop
// gives 28 independent coalesced LDGs in flight.
// ---------------------------------------------------------------------------
__global__ void roi_align_kernel(const float* __restrict__ f0,
                                 const float* __restrict__ f1,
                                 const float* __restrict__ f2,
                                 const float* __restrict__ f3,
                                 float* __restrict__ out) {
    int roi = blockIdx.x;
    int py  = blockIdx.y;
    int c   = threadIdx.x;

    float4 b = g_sbox[roi];
    int lvl = g_slvl[roi];

    const float* f = (lvl == 0) ? f0 : (lvl == 1) ? f1 : (lvl == 2) ? f2 : f3;
    int H = 256 >> lvl;
    int W = H;
    float Hm1 = (float)(H - 1);
    float Wm1 = (float)(W - 1);

    float iy = b.x * Hm1 + (float)py * ((b.z - b.x) * Hm1 * (1.0f / (PH - 1)));
    float y0f = floorf(iy);
    float ly = iy - y0f;
    int y0 = min(max((int)y0f, 0), H - 1);
    int y1 = min(max((int)y0f + 1, 0), H - 1);
    bool vy = (iy >= 0.0f) && (iy <= Hm1);

    const float* row0 = f + (size_t)y0 * W * C + c;
    const float* row1 = f + (size_t)y1 * W * C + c;
    float* o = out + ((size_t)(roi * PH + py) * PW) * C + c;

    float xstep = (b.w - b.y) * Wm1 * (1.0f / (PW - 1));
    float xbase = b.y * Wm1;

#pragma unroll
    for (int px = 0; px < PW; px++) {
        float ix = xbase + (float)px * xstep;
        float x0f = floorf(ix);
        float lx = ix - x0f;
        int x0 = min(max((int)x0f, 0), W - 1);
        int x1 = min(max((int)x0f + 1, 0), W - 1);
        bool vx = (ix >= 0.0f) && (ix <= Wm1);

        float f00 = __ldg(row0 + x0 * C);
        float f01 = __ldg(row0 + x1 * C);
        float f10 = __ldg(row1 + x0 * C);
        float f11 = __ldg(row1 + x1 * C);

        float top = fmaf(f01 - f00, lx, f00);
        float bot = fmaf(f11 - f10, lx, f10);
        float val = fmaf(bot - top, ly, top);

        o[px * C] = (vy && vx) ? val : 0.0f;
    }
}

extern "C" void kernel_launch(void* const* d_in, const int* in_sizes, int n_in,
                              void* d_out, int out_size) {
    const float* f0   = (const float*)d_in[0];
    const float* f1   = (const float*)d_in[1];
    const float* f2   = (const float*)d_in[2];
    const float* f3   = (const float*)d_in[3];
    const float* rois = (const float*)d_in[4];
    float* out = (float*)d_out;

    int N = in_sizes[4] / 4;
    if (N > MAXN) N = MAXN;

    level_sort_kernel<<<1, 1024>>>(rois, N);

    dim3 grid(N, PH);
    roi_align_kernel<<<grid, C>>>(f0, f1, f2, f3, out);
}

// round 5
// speedup vs baseline: 1.4375x; 1.4375x over previous
#include <cuda_runtime.h>
#include <math.h>

#define PH 7
#define PW 7
#define C  256
#define C4 (C / 4)
#define MAXN 1024

// Scratch (device globals; no allocation allowed)
__device__ float4 g_sbox[MAXN];   // sorted normalized boxes (y1,x1,y2,x2)
__device__ int    g_slvl[MAXN];   // sorted levels

// ---------------------------------------------------------------------------
// Kernel 1: per-roi level + normalized box, stable counting sort.
// Packed 4x16-bit counters in uint64; warp-shuffle inclusive scan + warp-total
// combine. Single block, 1024 threads, N <= 1024.
// ---------------------------------------------------------------------------
__global__ void level_sort_kernel(const float* __restrict__ rois, int N) {
    __shared__ unsigned long long warp_tot[32];
    int i    = threadIdx.x;
    int lane = i & 31;
    int wid  = i >> 5;

    int lvl = 0;
    float4 nb = make_float4(0.f, 0.f, 0.f, 0.f);
    unsigned long long v = 0ULL;

    if (i < N) {
        float y1 = rois[i * 4 + 0];
        float x1 = rois[i * 4 + 1];
        float y2 = rois[i * 4 + 2];
        float x2 = rois[i * 4 + 3];
        float h = y2 - y1;
        float w = x2 - x1;
        // match reference fp32 path: log(sqrt(h*w))/log(2) - 5, round-half-even
        float lf = logf(sqrtf(h * w)) * (1.0f / logf(2.0f)) - 5.0f;
        int l = (int)rintf(lf);
        l = min(max(l, 0), 3);
        lvl = l;
        const float inv = 1.0f / 1024.0f;
        nb = make_float4(y1 * inv, x1 * inv, y2 * inv, x2 * inv);
        v = 1ULL << (16 * lvl);
    }

    // warp inclusive scan (64-bit)
    unsigned long long incl = v;
#pragma unroll
    for (int off = 1; off < 32; off <<= 1) {
        unsigned long long t = __shfl_up_sync(0xFFFFFFFFu, incl, off);
        if (lane >= off) incl += t;
    }
    if (lane == 31) warp_tot[wid] = incl;
    __syncthreads();

    // warp 0 scans the 32 warp totals (inclusive)
    if (wid == 0) {
        unsigned long long wt = warp_tot[lane];
#pragma unroll
        for (int off = 1; off < 32; off <<= 1) {
            unsigned long long t = __shfl_up_sync(0xFFFFFFFFu, wt, off);
            if (lane >= off) wt += t;
        }
        warp_tot[lane] = wt;
    }
    __syncthreads();

    unsigned long long total = warp_tot[31];
    unsigned long long offset = (wid > 0) ? warp_tot[wid - 1] : 0ULL;
    incl += offset;

    if (i < N) {
        int rank = (int)((incl >> (16 * lvl)) & 0xFFFFULL) - 1;  // exclusive rank in level
        int base = 0;
#pragma unroll
        for (int l = 0; l < 4; l++)
            if (l < lvl) base += (int)((total >> (16 * l)) & 0xFFFFULL);
        int pos = base + rank;
        g_slvl[pos] = lvl;
        g_sbox[pos] = nb;
    }
}

// ---------------------------------------------------------------------------
// Kernel 2: bilinear crop_and_resize gather, float4-vectorized over channels.
// grid = (N, PH); blockDim = 64. Thread = 4-channel group; unrolled px loop
// gives 28 independent LDG.128 in flight per thread.
// ---------------------------------------------------------------------------
__global__ void __launch_bounds__(64, 8)
roi_align_kernel(const float* __restrict__ f0,
                 const float* __restrict__ f1,
                 const float* __restrict__ f2,
                 const float* __restrict__ f3,
                 float* __restrict__ out) {
    int roi = blockIdx.x;
    int py  = blockIdx.y;
    int c4  = threadIdx.x;   // 0..63 -> channel group of 4

    float4 b = g_sbox[roi];
    int lvl = g_slvl[roi];

    const float* f = (lvl == 0) ? f0 : (lvl == 1) ? f1 : (lvl == 2) ? f2 : f3;
    int H = 256 >> lvl;
    int W = H;
    float Hm1 = (float)(H - 1);
    float Wm1 = (float)(W - 1);

    float iy = b.x * Hm1 + (float)py * ((b.z - b.x) * Hm1 * (1.0f / (PH - 1)));
    float y0f = floorf(iy);
    float ly = iy - y0f;
    int y0 = min(max((int)y0f, 0), H - 1);
    int y1 = min(max((int)y0f + 1, 0), H - 1);
    bool vy = (iy >= 0.0f) && (iy <= Hm1);

    const float4* row0 = (const float4*)f + (size_t)y0 * W * C4 + c4;
    const float4* row1 = (const float4*)f + (size_t)y1 * W * C4 + c4;
    float4* o = (float4*)out + ((size_t)(roi * PH + py) * PW) * C4 + c4;

    float xstep = (b.w - b.y) * Wm1 * (1.0f / (PW - 1));
    float xbase = b.y * Wm1;

#pragma unroll
    for (int px = 0; px < PW; px++) {
        float ix = xbase + (float)px * xstep;
        float x0f = floorf(ix);
        float lx = ix - x0f;
        int x0 = min(max((int)x0f, 0), W - 1);
        int x1 = min(max((int)x0f + 1, 0), W - 1);
        bool vx = (ix >= 0.0f) && (ix <= Wm1);

        float4 f00 = __ldg(row0 + x0 * C4);
        float4 f01 = __ldg(row0 + x1 * C4);
        float4 f10 = __ldg(row1 + x0 * C4);
        float4 f11 = __ldg(row1 + x1 * C4);

        float4 r;
        float top, bot;
        top = fmaf(f01.x - f00.x, lx, f00.x);
        bot = fmaf(f11.x - f10.x, lx, f10.x);
        r.x = fmaf(bot - top, ly, top);
        top = fmaf(f01.y - f00.y, lx, f00.y);
        bot = fmaf(f11.y - f10.y, lx, f10.y);
        r.y = fmaf(bot - top, ly, top);
        top = fmaf(f01.z - f00.z, lx, f00.z);
        bot = fmaf(f11.z - f10.z, lx, f10.z);
        r.z = fmaf(bot - top, ly, top);
        top = fmaf(f01.w - f00.w, lx, f00.w);
        bot = fmaf(f11.w - f10.w, lx, f10.w);
        r.w = fmaf(bot - top, ly, top);

        if (!(vy && vx)) r = make_float4(0.f, 0.f, 0.f, 0.f);
        o[px * C4] = r;
    }
}

extern "C" void kernel_launch(void* const* d_in, const int* in_sizes, int n_in,
                              void* d_out, int out_size) {
    const float* f0   = (const float*)d_in[0];
    const float* f1   = (const float*)d_in[1];
    const float* f2   = (const float*)d_in[2];
    const float* f3   = (const float*)d_in[3];
    const float* rois = (const float*)d_in[4];
    float* out = (float*)d_out;

    int N = in_sizes[4] / 4;
    if (N > MAXN) N = MAXN;

    level_sort_kernel<<<1, 1024>>>(rois, N);

    dim3 grid(N, PH);
    roi_align_kernel<<<grid, 64>>>(f0, f1, f2, f3, out);
}